// round 13
// baseline (speedup 1.0000x reference)
#include <cuda_runtime.h>
#include <cuda_fp16.h>
#include <cstdint>

#define NH 16
#define SL 4096
#define HD 64
#define QT 128                 // q rows per CTA (32 per warp)
#define KT 64
#define NKT (SL / KT)          // 64
#define TSB 144                // smem row stride bytes (72 fp16)
#define TILEQ (128 * TSB)
#define TILEK (64 * TSB)

#define OFF_Q  0
#define OFF_K0 TILEQ
#define OFF_K1 (TILEQ + TILEK)
#define OFF_V0 (TILEQ + 2 * TILEK)
#define OFF_V1 (TILEQ + 3 * TILEK)
#define SMEM_BYTES (TILEQ + 4 * TILEK + 256)

#define ELEMS (NH * SL * HD)

__device__ __align__(16) __half g_qh[ELEMS];   // q * 0.125 * log2(e)
__device__ __align__(16) __half g_kh[ELEMS];
__device__ __align__(16) __half g_vh[ELEMS];

static __device__ __forceinline__ uint32_t smem_u32(const void* p) {
    uint32_t a;
    asm("{ .reg .u64 t; cvta.to.shared.u64 t, %1; cvt.u32.u64 %0, t; }" : "=r"(a) : "l"(p));
    return a;
}
static __device__ __forceinline__ void ldm_x4(uint32_t* r, uint32_t a) {
    asm volatile("ldmatrix.sync.aligned.m8n8.x4.shared.b16 {%0,%1,%2,%3}, [%4];"
                 : "=r"(r[0]), "=r"(r[1]), "=r"(r[2]), "=r"(r[3]) : "r"(a));
}
static __device__ __forceinline__ void ldm_x4t(uint32_t* r, uint32_t a) {
    asm volatile("ldmatrix.sync.aligned.m8n8.x4.trans.shared.b16 {%0,%1,%2,%3}, [%4];"
                 : "=r"(r[0]), "=r"(r[1]), "=r"(r[2]), "=r"(r[3]) : "r"(a));
}
static __device__ __forceinline__ void mma16816(float* d, const uint32_t* a, const uint32_t* b) {
    asm volatile("mma.sync.aligned.m16n8k16.row.col.f32.f16.f16.f32 "
                 "{%0,%1,%2,%3}, {%4,%5,%6,%7}, {%8,%9}, {%0,%1,%2,%3};"
                 : "+f"(d[0]), "+f"(d[1]), "+f"(d[2]), "+f"(d[3])
                 : "r"(a[0]), "r"(a[1]), "r"(a[2]), "r"(a[3]), "r"(b[0]), "r"(b[1]));
}
static __device__ __forceinline__ float ex2f(float x) {
    float y;
    asm("ex2.approx.f32 %0, %1;" : "=f"(y) : "f"(x));
    return y;
}
static __device__ __forceinline__ uint32_t ex2h2(uint32_t x) {
    uint32_t y;
    asm("ex2.approx.f16x2 %0, %1;" : "=r"(y) : "r"(x));
    return y;
}
static __device__ __forceinline__ uint32_t pack_h2(float a, float b) {
    __half2 t = __float22half2_rn(make_float2(a, b));
    return *reinterpret_cast<uint32_t*>(&t);
}
static __device__ __forceinline__ void cpa16(uint32_t dst, const void* src) {
    asm volatile("cp.async.cg.shared.global [%0], [%1], 16;" :: "r"(dst), "l"(src));
}
static __device__ __forceinline__ void cp_commit() {
    asm volatile("cp.async.commit_group;" ::: "memory");
}
template <int N> static __device__ __forceinline__ void cp_wait() {
    asm volatile("cp.async.wait_group %0;" :: "n"(N) : "memory");
}
static __device__ __forceinline__ void cp_tileK(uint32_t dsts, const __half* g, int tid) {
#pragma unroll
    for (int i = 0; i < 4; i++) {
        int idx = tid + i * 128;
        int row = idx >> 3;
        int ch  = idx & 7;
        cpa16(dsts + (uint32_t)row * TSB + (uint32_t)ch * 16,
              (const char*)g + row * 128 + ch * 16);
    }
}
static __device__ __forceinline__ void cp_tileQ(uint32_t dsts, const __half* g, int tid) {
#pragma unroll
    for (int i = 0; i < 8; i++) {
        int idx = tid + i * 128;
        int row = idx >> 3;
        int ch  = idx & 7;
        cpa16(dsts + (uint32_t)row * TSB + (uint32_t)ch * 16,
              (const char*)g + row * 128 + ch * 16);
    }
}

__global__ __launch_bounds__(256)
void prep_split_kernel(const float* __restrict__ q, const float* __restrict__ k,
                       const float* __restrict__ v)
{
    const float CS = 0.125f * 1.4426950408889634f;
    uint32_t i = blockIdx.x * 256 + threadIdx.x;
    float4 f;
    f = ((const float4*)q)[i];
    ((uint2*)g_qh)[i] = make_uint2(pack_h2(f.x * CS, f.y * CS), pack_h2(f.z * CS, f.w * CS));
    f = ((const float4*)k)[i];
    ((uint2*)g_kh)[i] = make_uint2(pack_h2(f.x, f.y), pack_h2(f.z, f.w));
    f = ((const float4*)v)[i];
    ((uint2*)g_vh)[i] = make_uint2(pack_h2(f.x, f.y), pack_h2(f.z, f.w));
}

__global__ __launch_bounds__(128, 2)
void attn_mma_kernel(float* __restrict__ out, float* __restrict__ score)
{
    extern __shared__ char smc[];
    const uint32_t sb = smem_u32(smc);

    const int qt   = blockIdx.x;
    const int h    = blockIdx.y;
    const int tid  = threadIdx.x;
    const int wid  = tid >> 5;
    const int lane = tid & 31;
    const int m0   = wid << 5;          // 32 q-rows per warp
    const int g    = lane >> 2;
    const int c    = lane & 3;

    const size_t hoff = (size_t)h * SL * HD;
    const __half* kh = g_kh + hoff;
    const __half* vh = g_vh + hoff;

    const uint32_t kstage[2] = {sb + OFF_K0, sb + OFF_K1};
    const uint32_t vstage[2] = {sb + OFF_V0, sb + OFF_V1};

    cp_tileQ(sb + OFF_Q, g_qh + hoff + (size_t)qt * QT * HD, tid);
    cp_commit();
    cp_tileK(kstage[0], kh, tid);
    cp_tileK(vstage[0], vh, tid);
    cp_commit();
    cp_tileK(kstage[1], kh + (size_t)KT * HD, tid);
    cp_tileK(vstage[1], vh + (size_t)KT * HD, tid);
    cp_commit();

    const uint32_t boff_row = (uint32_t)((lane & 7) + (((lane >> 4) & 1) << 3));
    const uint32_t boff_col = (uint32_t)(((lane >> 3) & 1) << 3) * 2;
    const uint32_t voff_row = (uint32_t)((lane & 7) + (((lane >> 3) & 1) << 3));
    const uint32_t voff_col = (uint32_t)(((lane >> 4) & 1) << 3) * 2;

    cp_wait<2>();      // Q ready
    __syncthreads();
    uint32_t Qh[2][4][4];
#pragma unroll
    for (int r = 0; r < 2; r++) {
        uint32_t ao = (uint32_t)(m0 + 16 * r + (lane & 15)) * TSB
                    + (uint32_t)((lane >> 4) << 3) * 2;
#pragma unroll
        for (int kk = 0; kk < 4; kk++)
            ldm_x4(Qh[r][kk], sb + OFF_Q + ao + (uint32_t)kk * 32);
    }

    float oacc[2][8][4] = {};
    float racc[2][4] = {};                   // rowsum accumulators (via P*ones MMA)
    const uint32_t ones2[2] = {0x3C003C00u, 0x3C003C00u};

    // ================= Phase A =================
    for (int kt = 0; kt < NKT; kt++) {
        cp_wait<1>();              // K(kt),V(kt) resident
        __syncthreads();
        const uint32_t bK = kstage[kt & 1];
        const uint32_t bV = vstage[kt & 1];

        // S = Q K^T (full tile)
        float sacc[2][8][4] = {};
#pragma unroll
        for (int kk = 0; kk < 4; kk++) {
#pragma unroll
            for (int t2 = 0; t2 < 4; t2++) {
                uint32_t boff = ((uint32_t)(t2 << 4) + boff_row) * TSB
                              + (uint32_t)(kk << 4) * 2 + boff_col;
                uint32_t Bh[4];
                ldm_x4(Bh, bK + boff);
#pragma unroll
                for (int r = 0; r < 2; r++) {
                    mma16816(sacc[r][2 * t2],     Qh[r][kk], Bh);
                    mma16816(sacc[r][2 * t2 + 1], Qh[r][kk], Bh + 2);
                }
            }
        }

        // P = ex2(S) directly in packed fp16 (f16x2 MUFU, half the ops)
        uint32_t Pp[2][16];
#pragma unroll
        for (int r = 0; r < 2; r++) {
#pragma unroll
            for (int t = 0; t < 8; t++) {
                int kk2 = t >> 1;
                int hf  = t & 1;
                Pp[r][4 * kk2 + 2 * hf]     = ex2h2(pack_h2(sacc[r][t][0], sacc[r][t][1]));
                Pp[r][4 * kk2 + 2 * hf + 1] = ex2h2(pack_h2(sacc[r][t][2], sacc[r][t][3]));
            }
        }

        // rowsums via tensor core: racc += P * ones
#pragma unroll
        for (int kk2 = 0; kk2 < 4; kk2++)
#pragma unroll
            for (int r = 0; r < 2; r++)
                mma16816(racc[r], &Pp[r][4 * kk2], ones2);

        // O += P V
#pragma unroll
        for (int kk2 = 0; kk2 < 4; kk2++) {
#pragma unroll
            for (int t2 = 0; t2 < 4; t2++) {
                uint32_t boff = ((uint32_t)(kk2 << 4) + voff_row) * TSB
                              + (uint32_t)(t2 << 4) * 2 + voff_col;
                uint32_t Bh[4];
                ldm_x4t(Bh, bV + boff);
#pragma unroll
                for (int r = 0; r < 2; r++) {
                    mma16816(oacc[r][2 * t2],     &Pp[r][4 * kk2], Bh);
                    mma16816(oacc[r][2 * t2 + 1], &Pp[r][4 * kk2], Bh + 2);
                }
            }
        }

        __syncthreads();           // stage kt&1 fully consumed
        if (kt + 2 < NKT) {
            cp_tileK(kstage[kt & 1], kh + (size_t)(kt + 2) * KT * HD, tid);
            cp_tileK(vstage[kt & 1], vh + (size_t)(kt + 2) * KT * HD, tid);
        }
        cp_commit();
    }
    cp_wait<0>();
    __syncthreads();

    // Phase B preload (K only)
    cp_tileK(kstage[0], kh, tid);
    cp_commit();
    cp_tileK(kstage[1], kh + (size_t)KT * HD, tid);
    cp_commit();

    // every lane already holds the full rowsums (MMA reduced over k)
    float inv[2][2], lg[2][2];
#pragma unroll
    for (int r = 0; r < 2; r++) {
        inv[r][0] = 1.0f / racc[r][0];  lg[r][0] = -__log2f(racc[r][0]);
        inv[r][1] = 1.0f / racc[r][2];  lg[r][1] = -__log2f(racc[r][2]);
    }

    {
        float* og = out + ((size_t)h * SL + (size_t)qt * QT) * HD;
#pragma unroll
        for (int r = 0; r < 2; r++) {
            float* r0p = og + (size_t)(m0 + 16 * r + g) * HD;
            float* r1p = og + (size_t)(m0 + 16 * r + g + 8) * HD;
#pragma unroll
            for (int nt = 0; nt < 8; nt++) {
                *(float2*)(r0p + nt * 8 + 2 * c) =
                    make_float2(oacc[r][nt][0] * inv[r][0], oacc[r][nt][1] * inv[r][0]);
                *(float2*)(r1p + nt * 8 + 2 * c) =
                    make_float2(oacc[r][nt][2] * inv[r][1], oacc[r][nt][3] * inv[r][1]);
            }
        }
    }

    // ================= Phase B: recompute S, write normalized score =================
    float* sg = score + (size_t)h * SL * SL + (size_t)qt * QT * SL;
    for (int kt = 0; kt < NKT; kt++) {
        cp_wait<1>();
        __syncthreads();
        const uint32_t bK = kstage[kt & 1];

        float sacc[2][8][4] = {};
#pragma unroll
        for (int kk = 0; kk < 4; kk++) {
#pragma unroll
            for (int t2 = 0; t2 < 4; t2++) {
                uint32_t boff = ((uint32_t)(t2 << 4) + boff_row) * TSB
                              + (uint32_t)(kk << 4) * 2 + boff_col;
                uint32_t Bh[4];
                ldm_x4(Bh, bK + boff);
#pragma unroll
                for (int r = 0; r < 2; r++) {
                    mma16816(sacc[r][2 * t2],     Qh[r][kk], Bh);
                    mma16816(sacc[r][2 * t2 + 1], Qh[r][kk], Bh + 2);
                }
            }
        }

        float* sgk = sg + (size_t)kt * KT;
#pragma unroll
        for (int r = 0; r < 2; r++) {
            float* r0p = sgk + (size_t)(m0 + 16 * r + g) * SL + 2 * c;
            float* r1p = sgk + (size_t)(m0 + 16 * r + g + 8) * SL + 2 * c;
#pragma unroll
            for (int t = 0; t < 8; t++) {
                *(float2*)(r0p + t * 8) =
                    make_float2(ex2f(sacc[r][t][0] + lg[r][0]),
                                ex2f(sacc[r][t][1] + lg[r][0]));
                *(float2*)(r1p + t * 8) =
                    make_float2(ex2f(sacc[r][t][2] + lg[r][1]),
                                ex2f(sacc[r][t][3] + lg[r][1]));
            }
        }

        __syncthreads();
        if (kt + 2 < NKT)
            cp_tileK(kstage[kt & 1], kh + (size_t)(kt + 2) * KT * HD, tid);
        cp_commit();
    }
}

extern "C" void kernel_launch(void* const* d_in, const int* in_sizes, int n_in,
                              void* d_out, int out_size)
{
    const float* q = (const float*)d_in[0];
    const float* k = (const float*)d_in[1];
    const float* v = (const float*)d_in[2];
    float* out   = (float*)d_out;
    float* score = out + (size_t)NH * SL * HD;

    prep_split_kernel<<<ELEMS / 4 / 256, 256>>>(q, k, v);

    cudaFuncSetAttribute(attn_mma_kernel,
                         cudaFuncAttributeMaxDynamicSharedMemorySize, SMEM_BYTES);
    dim3 grid(SL / QT, NH);
    attn_mma_kernel<<<grid, 128, SMEM_BYTES>>>(out, score);
}

// round 16
// speedup vs baseline: 1.0238x; 1.0238x over previous
#include <cuda_runtime.h>
#include <cuda_fp16.h>
#include <cstdint>

#define NH 16
#define SL 4096
#define HD 64
#define QT 128                 // q rows per CTA (32 per warp)
#define KT 64
#define NKT (SL / KT)          // 64
#define TSB 144                // smem row stride bytes (72 fp16)
#define TILEQ (128 * TSB)
#define TILEK (64 * TSB)

// smem: Q + 3 K stages + 3 V stages + rowsum
#define OFF_Q  0
#define OFF_K(i) (TILEQ + (i) * TILEK)
#define OFF_V(i) (TILEQ + (3 + (i)) * TILEK)
#define OFF_ROWSUM (TILEQ + 6 * TILEK)
#define SMEM_BYTES (OFF_ROWSUM + 768)   // ~73.5 KB -> 2 CTAs/SM

#define ELEMS (NH * SL * HD)

__device__ __align__(16) __half g_qh[ELEMS];   // q * 0.125 * log2(e)
__device__ __align__(16) __half g_kh[ELEMS];
__device__ __align__(16) __half g_vh[ELEMS];

static __device__ __forceinline__ uint32_t smem_u32(const void* p) {
    uint32_t a;
    asm("{ .reg .u64 t; cvta.to.shared.u64 t, %1; cvt.u32.u64 %0, t; }" : "=r"(a) : "l"(p));
    return a;
}
static __device__ __forceinline__ void ldm_x4(uint32_t* r, uint32_t a) {
    asm volatile("ldmatrix.sync.aligned.m8n8.x4.shared.b16 {%0,%1,%2,%3}, [%4];"
                 : "=r"(r[0]), "=r"(r[1]), "=r"(r[2]), "=r"(r[3]) : "r"(a));
}
static __device__ __forceinline__ void ldm_x4t(uint32_t* r, uint32_t a) {
    asm volatile("ldmatrix.sync.aligned.m8n8.x4.trans.shared.b16 {%0,%1,%2,%3}, [%4];"
                 : "=r"(r[0]), "=r"(r[1]), "=r"(r[2]), "=r"(r[3]) : "r"(a));
}
static __device__ __forceinline__ void mma16816(float* d, const uint32_t* a, const uint32_t* b) {
    asm volatile("mma.sync.aligned.m16n8k16.row.col.f32.f16.f16.f32 "
                 "{%0,%1,%2,%3}, {%4,%5,%6,%7}, {%8,%9}, {%0,%1,%2,%3};"
                 : "+f"(d[0]), "+f"(d[1]), "+f"(d[2]), "+f"(d[3])
                 : "r"(a[0]), "r"(a[1]), "r"(a[2]), "r"(a[3]), "r"(b[0]), "r"(b[1]));
}
static __device__ __forceinline__ float ex2f(float x) {
    float y;
    asm("ex2.approx.f32 %0, %1;" : "=f"(y) : "f"(x));
    return y;
}
static __device__ __forceinline__ uint32_t pack_h2(float a, float b) {
    __half2 t = __float22half2_rn(make_float2(a, b));
    return *reinterpret_cast<uint32_t*>(&t);
}
static __device__ __forceinline__ void cpa16(uint32_t dst, const void* src) {
    asm volatile("cp.async.cg.shared.global [%0], [%1], 16;" :: "r"(dst), "l"(src));
}
static __device__ __forceinline__ void cp_commit() {
    asm volatile("cp.async.commit_group;" ::: "memory");
}
template <int N> static __device__ __forceinline__ void cp_wait() {
    asm volatile("cp.async.wait_group %0;" :: "n"(N) : "memory");
}
static __device__ __forceinline__ void cp_tileK(uint32_t dsts, const __half* g, int tid) {
#pragma unroll
    for (int i = 0; i < 4; i++) {
        int idx = tid + i * 128;
        int row = idx >> 3;
        int ch  = idx & 7;
        cpa16(dsts + (uint32_t)row * TSB + (uint32_t)ch * 16,
              (const char*)g + row * 128 + ch * 16);
    }
}
static __device__ __forceinline__ void cp_tileQ(uint32_t dsts, const __half* g, int tid) {
#pragma unroll
    for (int i = 0; i < 8; i++) {
        int idx = tid + i * 128;
        int row = idx >> 3;
        int ch  = idx & 7;
        cpa16(dsts + (uint32_t)row * TSB + (uint32_t)ch * 16,
              (const char*)g + row * 128 + ch * 16);
    }
}

__global__ __launch_bounds__(256)
void prep_split_kernel(const float* __restrict__ q, const float* __restrict__ k,
                       const float* __restrict__ v)
{
    const float CS = 0.125f * 1.4426950408889634f;
    uint32_t i = blockIdx.x * 256 + threadIdx.x;
    float4 f;
    f = ((const float4*)q)[i];
    ((uint2*)g_qh)[i] = make_uint2(pack_h2(f.x * CS, f.y * CS), pack_h2(f.z * CS, f.w * CS));
    f = ((const float4*)k)[i];
    ((uint2*)g_kh)[i] = make_uint2(pack_h2(f.x, f.y), pack_h2(f.z, f.w));
    f = ((const float4*)v)[i];
    ((uint2*)g_vh)[i] = make_uint2(pack_h2(f.x, f.y), pack_h2(f.z, f.w));
}

__global__ __launch_bounds__(128, 2)
void attn_mma_kernel(float* __restrict__ out, float* __restrict__ score)
{
    extern __shared__ char smc[];
    const uint32_t sb = smem_u32(smc);

    const int qt   = blockIdx.x;
    const int h    = blockIdx.y;
    const int tid  = threadIdx.x;
    const int wid  = tid >> 5;
    const int lane = tid & 31;
    const int m0   = wid << 5;          // 32 q-rows per warp
    const int g    = lane >> 2;
    const int c    = lane & 3;

    const size_t hoff = (size_t)h * SL * HD;
    const __half* kh = g_kh + hoff;
    const __half* vh = g_vh + hoff;

    float* rowsum = (float*)(smc + OFF_ROWSUM);
    const uint32_t kst[3] = {sb + OFF_K(0), sb + OFF_K(1), sb + OFF_K(2)};
    const uint32_t vst[3] = {sb + OFF_V(0), sb + OFF_V(1), sb + OFF_V(2)};

    // prologue: Q | K0,V0 | K1,V1   (3 groups)
    cp_tileQ(sb + OFF_Q, g_qh + hoff + (size_t)qt * QT * HD, tid);
    cp_commit();
    cp_tileK(kst[0], kh, tid);
    cp_tileK(vst[0], vh, tid);
    cp_commit();
    cp_tileK(kst[1], kh + (size_t)KT * HD, tid);
    cp_tileK(vst[1], vh + (size_t)KT * HD, tid);
    cp_commit();

    const uint32_t boff_row = (uint32_t)((lane & 7) + (((lane >> 4) & 1) << 3));
    const uint32_t boff_col = (uint32_t)(((lane >> 3) & 1) << 3) * 2;
    const uint32_t voff_row = (uint32_t)((lane & 7) + (((lane >> 3) & 1) << 3));
    const uint32_t voff_col = (uint32_t)(((lane >> 4) & 1) << 3) * 2;

    cp_wait<2>();      // Q landed
    __syncthreads();
    uint32_t Qh[2][4][4];
#pragma unroll
    for (int r = 0; r < 2; r++) {
        uint32_t ao = (uint32_t)(m0 + 16 * r + (lane & 15)) * TSB
                    + (uint32_t)((lane >> 4) << 3) * 2;
#pragma unroll
        for (int kk = 0; kk < 4; kk++)
            ldm_x4(Qh[r][kk], sb + OFF_Q + ao + (uint32_t)kk * 32);
    }

    float oacc[2][8][4] = {};
    float rsum[2][2] = {};

    // ================= Phase A =================
    for (int kt = 0; kt < NKT; kt++) {
        // full-iteration prefetch distance: issue kt+2 NOW (buffer freed at end of kt-1)
        if (kt + 2 < NKT) {
            const int st = (kt + 2) % 3;
            cp_tileK(kst[st], kh + (size_t)(kt + 2) * KT * HD, tid);
            cp_tileK(vst[st], vh + (size_t)(kt + 2) * KT * HD, tid);
        }
        cp_commit();               // one group per iter (maybe empty)
        cp_wait<2>();              // K(kt),V(kt) landed
        __syncthreads();
        const uint32_t bK = kst[kt % 3];
        const uint32_t bV = vst[kt % 3];

        // S = Q K^T (full tile, long chains — R10 schedule)
        float sacc[2][8][4] = {};
#pragma unroll
        for (int kk = 0; kk < 4; kk++) {
#pragma unroll
            for (int t2 = 0; t2 < 4; t2++) {
                uint32_t boff = ((uint32_t)(t2 << 4) + boff_row) * TSB
                              + (uint32_t)(kk << 4) * 2 + boff_col;
                uint32_t Bh[4];
                ldm_x4(Bh, bK + boff);
#pragma unroll
                for (int r = 0; r < 2; r++) {
                    mma16816(sacc[r][2 * t2],     Qh[r][kk], Bh);
                    mma16816(sacc[r][2 * t2 + 1], Qh[r][kk], Bh + 2);
                }
            }
        }

        // exp + rowsums + pack (R10 structure; scale pre-folded into Q)
        uint32_t Pp[2][16];
#pragma unroll
        for (int r = 0; r < 2; r++) {
#pragma unroll
            for (int t = 0; t < 8; t++) {
                float e0 = ex2f(sacc[r][t][0]);
                float e1 = ex2f(sacc[r][t][1]);
                float e2 = ex2f(sacc[r][t][2]);
                float e3 = ex2f(sacc[r][t][3]);
                rsum[r][0] += e0 + e1;
                rsum[r][1] += e2 + e3;
                int kk2 = t >> 1;
                int hf  = t & 1;
                Pp[r][4 * kk2 + 2 * hf]     = pack_h2(e0, e1);
                Pp[r][4 * kk2 + 2 * hf + 1] = pack_h2(e2, e3);
            }
        }

        // O += P V
#pragma unroll
        for (int kk2 = 0; kk2 < 4; kk2++) {
#pragma unroll
            for (int t2 = 0; t2 < 4; t2++) {
                uint32_t boff = ((uint32_t)(kk2 << 4) + voff_row) * TSB
                              + (uint32_t)(t2 << 4) * 2 + voff_col;
                uint32_t Bh[4];
                ldm_x4t(Bh, bV + boff);
#pragma unroll
                for (int r = 0; r < 2; r++) {
                    mma16816(oacc[r][2 * t2],     &Pp[r][4 * kk2], Bh);
                    mma16816(oacc[r][2 * t2 + 1], &Pp[r][4 * kk2], Bh + 2);
                }
            }
        }
        __syncthreads();   // readers done with stage kt%3 (rewritten at kt+1's prefetch of kt+3)
    }
    cp_wait<0>();
    __syncthreads();

#pragma unroll
    for (int r = 0; r < 2; r++) {
#pragma unroll
        for (int s = 0; s < 2; s++) {
            float v = rsum[r][s];
            v += __shfl_xor_sync(0xffffffffu, v, 1);
            v += __shfl_xor_sync(0xffffffffu, v, 2);
            if (c == 0) rowsum[m0 + 16 * r + 8 * s + g] = v;
        }
    }
    __syncthreads();

    // Phase B preloads overlap the O write
    cp_tileK(kst[0], kh, tid);
    cp_commit();
    cp_tileK(kst[1], kh + (size_t)KT * HD, tid);
    cp_commit();

    float inv[2][2], lg[2][2];
#pragma unroll
    for (int r = 0; r < 2; r++) {
#pragma unroll
        for (int s = 0; s < 2; s++) {
            float rs = rowsum[m0 + 16 * r + 8 * s + g];
            inv[r][s] = 1.0f / rs;
            lg[r][s]  = -__log2f(rs);
        }
    }

    {
        float* og = out + ((size_t)h * SL + (size_t)qt * QT) * HD;
#pragma unroll
        for (int r = 0; r < 2; r++) {
            float* r0p = og + (size_t)(m0 + 16 * r + g) * HD;
            float* r1p = og + (size_t)(m0 + 16 * r + g + 8) * HD;
#pragma unroll
            for (int nt = 0; nt < 8; nt++) {
                *(float2*)(r0p + nt * 8 + 2 * c) =
                    make_float2(oacc[r][nt][0] * inv[r][0], oacc[r][nt][1] * inv[r][0]);
                *(float2*)(r1p + nt * 8 + 2 * c) =
                    make_float2(oacc[r][nt][2] * inv[r][1], oacc[r][nt][3] * inv[r][1]);
            }
        }
    }

    // ================= Phase B: recompute S, write normalized score =================
    float* sg = score + (size_t)h * SL * SL + (size_t)qt * QT * SL;
    for (int kt = 0; kt < NKT; kt++) {
        if (kt + 2 < NKT)
            cp_tileK(kst[(kt + 2) % 3], kh + (size_t)(kt + 2) * KT * HD, tid);
        cp_commit();
        cp_wait<2>();
        __syncthreads();
        const uint32_t bK = kst[kt % 3];

        float sacc[2][8][4] = {};
#pragma unroll
        for (int kk = 0; kk < 4; kk++) {
#pragma unroll
            for (int t2 = 0; t2 < 4; t2++) {
                uint32_t boff = ((uint32_t)(t2 << 4) + boff_row) * TSB
                              + (uint32_t)(kk << 4) * 2 + boff_col;
                uint32_t Bh[4];
                ldm_x4(Bh, bK + boff);
#pragma unroll
                for (int r = 0; r < 2; r++) {
                    mma16816(sacc[r][2 * t2],     Qh[r][kk], Bh);
                    mma16816(sacc[r][2 * t2 + 1], Qh[r][kk], Bh + 2);
                }
            }
        }

        float* sgk = sg + (size_t)kt * KT;
#pragma unroll
        for (int r = 0; r < 2; r++) {
            float* r0p = sgk + (size_t)(m0 + 16 * r + g) * SL + 2 * c;
            float* r1p = sgk + (size_t)(m0 + 16 * r + g + 8) * SL + 2 * c;
#pragma unroll
            for (int t = 0; t < 8; t++) {
                *(float2*)(r0p + t * 8) =
                    make_float2(ex2f(sacc[r][t][0] + lg[r][0]),
                                ex2f(sacc[r][t][1] + lg[r][0]));
                *(float2*)(r1p + t * 8) =
                    make_float2(ex2f(sacc[r][t][2] + lg[r][1]),
                                ex2f(sacc[r][t][3] + lg[r][1]));
            }
        }
        __syncthreads();
    }
}

extern "C" void kernel_launch(void* const* d_in, const int* in_sizes, int n_in,
                              void* d_out, int out_size)
{
    const float* q = (const float*)d_in[0];
    const float* k = (const float*)d_in[1];
    const float* v = (const float*)d_in[2];
    float* out   = (float*)d_out;
    float* score = out + (size_t)NH * SL * HD;

    prep_split_kernel<<<ELEMS / 4 / 256, 256>>>(q, k, v);

    cudaFuncSetAttribute(attn_mma_kernel,
                         cudaFuncAttributeMaxDynamicSharedMemorySize, SMEM_BYTES);
    dim3 grid(SL / QT, NH);
    attn_mma_kernel<<<grid, 128, SMEM_BYTES>>>(out, score);
}

// round 17
// speedup vs baseline: 1.1213x; 1.0952x over previous
#include <cuda_runtime.h>
#include <cuda_fp16.h>
#include <cstdint>

#define NH 16
#define SL 4096
#define HD 64
#define QT 128                 // q rows per CTA (32 per warp)
#define KT 64
#define NKT (SL / KT)          // 64
#define TSB 144                // smem row stride bytes (72 fp16)
#define TILEQ (128 * TSB)
#define TILEK (64 * TSB)

// kernel A smem: Q + 3 K stages + 3 V stages + rowsum
#define OFF_Q  0
#define OFF_K(i) (TILEQ + (i) * TILEK)
#define OFF_V(i) (TILEQ + (3 + (i)) * TILEK)
#define OFF_ROWSUM (TILEQ + 6 * TILEK)
#define SMEM_A (OFF_ROWSUM + 768)

// kernel B smem: Q + 3 K stages
#define SMEM_B (TILEQ + 3 * TILEK + 256)

#define CHUNK 8                // k-tiles per Phase-B CTA
#define ELEMS (NH * SL * HD)

__device__ __align__(16) __half g_qh[ELEMS];   // q * 0.125 * log2(e)
__device__ __align__(16) __half g_kh[ELEMS];
__device__ __align__(16) __half g_vh[ELEMS];
__device__ float g_lg[NH * SL];                // -log2(rowsum)

static __device__ __forceinline__ uint32_t smem_u32(const void* p) {
    uint32_t a;
    asm("{ .reg .u64 t; cvta.to.shared.u64 t, %1; cvt.u32.u64 %0, t; }" : "=r"(a) : "l"(p));
    return a;
}
static __device__ __forceinline__ void ldm_x4(uint32_t* r, uint32_t a) {
    asm volatile("ldmatrix.sync.aligned.m8n8.x4.shared.b16 {%0,%1,%2,%3}, [%4];"
                 : "=r"(r[0]), "=r"(r[1]), "=r"(r[2]), "=r"(r[3]) : "r"(a));
}
static __device__ __forceinline__ void ldm_x4t(uint32_t* r, uint32_t a) {
    asm volatile("ldmatrix.sync.aligned.m8n8.x4.trans.shared.b16 {%0,%1,%2,%3}, [%4];"
                 : "=r"(r[0]), "=r"(r[1]), "=r"(r[2]), "=r"(r[3]) : "r"(a));
}
static __device__ __forceinline__ void mma16816(float* d, const uint32_t* a, const uint32_t* b) {
    asm volatile("mma.sync.aligned.m16n8k16.row.col.f32.f16.f16.f32 "
                 "{%0,%1,%2,%3}, {%4,%5,%6,%7}, {%8,%9}, {%0,%1,%2,%3};"
                 : "+f"(d[0]), "+f"(d[1]), "+f"(d[2]), "+f"(d[3])
                 : "r"(a[0]), "r"(a[1]), "r"(a[2]), "r"(a[3]), "r"(b[0]), "r"(b[1]));
}
static __device__ __forceinline__ float ex2f(float x) {
    float y;
    asm("ex2.approx.f32 %0, %1;" : "=f"(y) : "f"(x));
    return y;
}
static __device__ __forceinline__ uint32_t pack_h2(float a, float b) {
    __half2 t = __float22half2_rn(make_float2(a, b));
    return *reinterpret_cast<uint32_t*>(&t);
}
static __device__ __forceinline__ void cpa16(uint32_t dst, const void* src) {
    asm volatile("cp.async.cg.shared.global [%0], [%1], 16;" :: "r"(dst), "l"(src));
}
static __device__ __forceinline__ void cp_commit() {
    asm volatile("cp.async.commit_group;" ::: "memory");
}
template <int N> static __device__ __forceinline__ void cp_wait() {
    asm volatile("cp.async.wait_group %0;" :: "n"(N) : "memory");
}
static __device__ __forceinline__ void cp_tileK(uint32_t dsts, const __half* g, int tid) {
#pragma unroll
    for (int i = 0; i < 4; i++) {
        int idx = tid + i * 128;
        int row = idx >> 3;
        int ch  = idx & 7;
        cpa16(dsts + (uint32_t)row * TSB + (uint32_t)ch * 16,
              (const char*)g + row * 128 + ch * 16);
    }
}
static __device__ __forceinline__ void cp_tileQ(uint32_t dsts, const __half* g, int tid) {
#pragma unroll
    for (int i = 0; i < 8; i++) {
        int idx = tid + i * 128;
        int row = idx >> 3;
        int ch  = idx & 7;
        cpa16(dsts + (uint32_t)row * TSB + (uint32_t)ch * 16,
              (const char*)g + row * 128 + ch * 16);
    }
}

__global__ __launch_bounds__(256)
void prep_split_kernel(const float* __restrict__ q, const float* __restrict__ k,
                       const float* __restrict__ v)
{
    const float CS = 0.125f * 1.4426950408889634f;
    uint32_t i = blockIdx.x * 256 + threadIdx.x;
    float4 f;
    f = ((const float4*)q)[i];
    ((uint2*)g_qh)[i] = make_uint2(pack_h2(f.x * CS, f.y * CS), pack_h2(f.z * CS, f.w * CS));
    f = ((const float4*)k)[i];
    ((uint2*)g_kh)[i] = make_uint2(pack_h2(f.x, f.y), pack_h2(f.z, f.w));
    f = ((const float4*)v)[i];
    ((uint2*)g_vh)[i] = make_uint2(pack_h2(f.x, f.y), pack_h2(f.z, f.w));
}

// ================= Kernel A: O + rowsums =================
__global__ __launch_bounds__(128, 2)
void attn_phaseA_kernel(float* __restrict__ out)
{
    extern __shared__ char smc[];
    const uint32_t sb = smem_u32(smc);

    const int qt   = blockIdx.x;
    const int h    = blockIdx.y;
    const int tid  = threadIdx.x;
    const int wid  = tid >> 5;
    const int lane = tid & 31;
    const int m0   = wid << 5;
    const int g    = lane >> 2;
    const int c    = lane & 3;

    const size_t hoff = (size_t)h * SL * HD;
    const __half* kh = g_kh + hoff;
    const __half* vh = g_vh + hoff;

    float* rowsum = (float*)(smc + OFF_ROWSUM);
    const uint32_t kst[3] = {sb + OFF_K(0), sb + OFF_K(1), sb + OFF_K(2)};
    const uint32_t vst[3] = {sb + OFF_V(0), sb + OFF_V(1), sb + OFF_V(2)};

    cp_tileQ(sb + OFF_Q, g_qh + hoff + (size_t)qt * QT * HD, tid);
    cp_commit();
    cp_tileK(kst[0], kh, tid);
    cp_tileK(vst[0], vh, tid);
    cp_commit();
    cp_tileK(kst[1], kh + (size_t)KT * HD, tid);
    cp_tileK(vst[1], vh + (size_t)KT * HD, tid);
    cp_commit();

    const uint32_t boff_row = (uint32_t)((lane & 7) + (((lane >> 4) & 1) << 3));
    const uint32_t boff_col = (uint32_t)(((lane >> 3) & 1) << 3) * 2;
    const uint32_t voff_row = (uint32_t)((lane & 7) + (((lane >> 3) & 1) << 3));
    const uint32_t voff_col = (uint32_t)(((lane >> 4) & 1) << 3) * 2;

    cp_wait<2>();
    __syncthreads();
    uint32_t Qh[2][4][4];
#pragma unroll
    for (int r = 0; r < 2; r++) {
        uint32_t ao = (uint32_t)(m0 + 16 * r + (lane & 15)) * TSB
                    + (uint32_t)((lane >> 4) << 3) * 2;
#pragma unroll
        for (int kk = 0; kk < 4; kk++)
            ldm_x4(Qh[r][kk], sb + OFF_Q + ao + (uint32_t)kk * 32);
    }

    float oacc[2][8][4] = {};
    float rsum[2][2] = {};

    for (int kt = 0; kt < NKT; kt++) {
        if (kt + 2 < NKT) {
            const int st = (kt + 2) % 3;
            cp_tileK(kst[st], kh + (size_t)(kt + 2) * KT * HD, tid);
            cp_tileK(vst[st], vh + (size_t)(kt + 2) * KT * HD, tid);
        }
        cp_commit();
        cp_wait<2>();
        __syncthreads();
        const uint32_t bK = kst[kt % 3];
        const uint32_t bV = vst[kt % 3];

        float sacc[2][8][4] = {};
#pragma unroll
        for (int kk = 0; kk < 4; kk++) {
#pragma unroll
            for (int t2 = 0; t2 < 4; t2++) {
                uint32_t boff = ((uint32_t)(t2 << 4) + boff_row) * TSB
                              + (uint32_t)(kk << 4) * 2 + boff_col;
                uint32_t Bh[4];
                ldm_x4(Bh, bK + boff);
#pragma unroll
                for (int r = 0; r < 2; r++) {
                    mma16816(sacc[r][2 * t2],     Qh[r][kk], Bh);
                    mma16816(sacc[r][2 * t2 + 1], Qh[r][kk], Bh + 2);
                }
            }
        }

        uint32_t Pp[2][16];
#pragma unroll
        for (int r = 0; r < 2; r++) {
#pragma unroll
            for (int t = 0; t < 8; t++) {
                float e0 = ex2f(sacc[r][t][0]);
                float e1 = ex2f(sacc[r][t][1]);
                float e2 = ex2f(sacc[r][t][2]);
                float e3 = ex2f(sacc[r][t][3]);
                rsum[r][0] += e0 + e1;
                rsum[r][1] += e2 + e3;
                int kk2 = t >> 1;
                int hf  = t & 1;
                Pp[r][4 * kk2 + 2 * hf]     = pack_h2(e0, e1);
                Pp[r][4 * kk2 + 2 * hf + 1] = pack_h2(e2, e3);
            }
        }

#pragma unroll
        for (int kk2 = 0; kk2 < 4; kk2++) {
#pragma unroll
            for (int t2 = 0; t2 < 4; t2++) {
                uint32_t boff = ((uint32_t)(kk2 << 4) + voff_row) * TSB
                              + (uint32_t)(t2 << 4) * 2 + voff_col;
                uint32_t Bh[4];
                ldm_x4t(Bh, bV + boff);
#pragma unroll
                for (int r = 0; r < 2; r++) {
                    mma16816(oacc[r][2 * t2],     &Pp[r][4 * kk2], Bh);
                    mma16816(oacc[r][2 * t2 + 1], &Pp[r][4 * kk2], Bh + 2);
                }
            }
        }
        __syncthreads();
    }
    cp_wait<0>();

#pragma unroll
    for (int r = 0; r < 2; r++) {
#pragma unroll
        for (int s = 0; s < 2; s++) {
            float v = rsum[r][s];
            v += __shfl_xor_sync(0xffffffffu, v, 1);
            v += __shfl_xor_sync(0xffffffffu, v, 2);
            if (c == 0) {
                rowsum[m0 + 16 * r + 8 * s + g] = v;
                g_lg[h * SL + qt * QT + m0 + 16 * r + 8 * s + g] = -__log2f(v);
            }
        }
    }
    __syncthreads();

    float inv[2][2];
#pragma unroll
    for (int r = 0; r < 2; r++) {
        inv[r][0] = 1.0f / rowsum[m0 + 16 * r + g];
        inv[r][1] = 1.0f / rowsum[m0 + 16 * r + g + 8];
    }

    float* og = out + ((size_t)h * SL + (size_t)qt * QT) * HD;
#pragma unroll
    for (int r = 0; r < 2; r++) {
        float* r0p = og + (size_t)(m0 + 16 * r + g) * HD;
        float* r1p = og + (size_t)(m0 + 16 * r + g + 8) * HD;
#pragma unroll
        for (int nt = 0; nt < 8; nt++) {
            *(float2*)(r0p + nt * 8 + 2 * c) =
                make_float2(oacc[r][nt][0] * inv[r][0], oacc[r][nt][1] * inv[r][0]);
            *(float2*)(r1p + nt * 8 + 2 * c) =
                make_float2(oacc[r][nt][2] * inv[r][1], oacc[r][nt][3] * inv[r][1]);
        }
    }
}

// ================= Kernel B: score writer (high occupancy) =================
__global__ __launch_bounds__(128, 3)
void attn_phaseB_kernel(float* __restrict__ score)
{
    extern __shared__ char smc[];
    const uint32_t sb = smem_u32(smc);

    const int qt    = blockIdx.x;          // 0..31
    const int chunk = blockIdx.y;          // 0..7
    const int h     = blockIdx.z;          // 0..15
    const int tid   = threadIdx.x;
    const int lane  = tid & 31;
    const int m0    = (tid >> 5) << 5;
    const int g     = lane >> 2;
    const int c     = lane & 3;

    const size_t hoff = (size_t)h * SL * HD;
    const __half* kh = g_kh + hoff;
    const int kt0 = chunk * CHUNK;

    const uint32_t kst[3] = {sb + TILEQ, sb + TILEQ + TILEK, sb + TILEQ + 2 * TILEK};

    cp_tileQ(sb, g_qh + hoff + (size_t)qt * QT * HD, tid);
    cp_commit();
    cp_tileK(kst[0], kh + (size_t)kt0 * KT * HD, tid);
    cp_commit();
    cp_tileK(kst[1], kh + (size_t)(kt0 + 1) * KT * HD, tid);
    cp_commit();

    const uint32_t boff_row = (uint32_t)((lane & 7) + (((lane >> 4) & 1) << 3));
    const uint32_t boff_col = (uint32_t)(((lane >> 3) & 1) << 3) * 2;

    cp_wait<2>();
    __syncthreads();
    uint32_t Qh[2][4][4];
#pragma unroll
    for (int r = 0; r < 2; r++) {
        uint32_t ao = (uint32_t)(m0 + 16 * r + (lane & 15)) * TSB
                    + (uint32_t)((lane >> 4) << 3) * 2;
#pragma unroll
        for (int kk = 0; kk < 4; kk++)
            ldm_x4(Qh[r][kk], sb + ao + (uint32_t)kk * 32);
    }

    float lg[2][2];
#pragma unroll
    for (int r = 0; r < 2; r++) {
        lg[r][0] = g_lg[h * SL + qt * QT + m0 + 16 * r + g];
        lg[r][1] = g_lg[h * SL + qt * QT + m0 + 16 * r + g + 8];
    }

    float* sg = score + (size_t)h * SL * SL + (size_t)qt * QT * SL;

    for (int i = 0; i < CHUNK; i++) {
        if (i + 2 < CHUNK)
            cp_tileK(kst[(i + 2) % 3], kh + (size_t)(kt0 + i + 2) * KT * HD, tid);
        cp_commit();
        cp_wait<2>();
        __syncthreads();
        const uint32_t bK = kst[i % 3];

        float sacc[2][8][4] = {};
#pragma unroll
        for (int kk = 0; kk < 4; kk++) {
#pragma unroll
            for (int t2 = 0; t2 < 4; t2++) {
                uint32_t boff = ((uint32_t)(t2 << 4) + boff_row) * TSB
                              + (uint32_t)(kk << 4) * 2 + boff_col;
                uint32_t Bh[4];
                ldm_x4(Bh, bK + boff);
#pragma unroll
                for (int r = 0; r < 2; r++) {
                    mma16816(sacc[r][2 * t2],     Qh[r][kk], Bh);
                    mma16816(sacc[r][2 * t2 + 1], Qh[r][kk], Bh + 2);
                }
            }
        }

        float* sgk = sg + (size_t)(kt0 + i) * KT;
#pragma unroll
        for (int r = 0; r < 2; r++) {
            float* r0p = sgk + (size_t)(m0 + 16 * r + g) * SL + 2 * c;
            float* r1p = sgk + (size_t)(m0 + 16 * r + g + 8) * SL + 2 * c;
#pragma unroll
            for (int t = 0; t < 8; t++) {
                *(float2*)(r0p + t * 8) =
                    make_float2(ex2f(sacc[r][t][0] + lg[r][0]),
                                ex2f(sacc[r][t][1] + lg[r][0]));
                *(float2*)(r1p + t * 8) =
                    make_float2(ex2f(sacc[r][t][2] + lg[r][1]),
                                ex2f(sacc[r][t][3] + lg[r][1]));
            }
        }
        __syncthreads();
    }
}

extern "C" void kernel_launch(void* const* d_in, const int* in_sizes, int n_in,
                              void* d_out, int out_size)
{
    const float* q = (const float*)d_in[0];
    const float* k = (const float*)d_in[1];
    const float* v = (const float*)d_in[2];
    float* out   = (float*)d_out;
    float* score = out + (size_t)NH * SL * HD;

    prep_split_kernel<<<ELEMS / 4 / 256, 256>>>(q, k, v);

    cudaFuncSetAttribute(attn_phaseA_kernel,
                         cudaFuncAttributeMaxDynamicSharedMemorySize, SMEM_A);
    cudaFuncSetAttribute(attn_phaseB_kernel,
                         cudaFuncAttributeMaxDynamicSharedMemorySize, SMEM_B);

    dim3 gridA(SL / QT, NH);
    attn_phaseA_kernel<<<gridA, 128, SMEM_A>>>(out);

    dim3 gridB(SL / QT, NKT / CHUNK, NH);
    attn_phaseB_kernel<<<gridB, 128, SMEM_B>>>(score);
}